// round 14
// baseline (speedup 1.0000x reference)
#include <cuda_runtime.h>
#include <cstdint>

#define B_ 64
#define C_ 1024
#define Q_ 128
#define H_ 256

// ---- scratch ----
__device__ float g_spart[B_ * 16 * H_];   // per-chunk beta-weighted ctx partial sums
__device__ float g_Ml[B_ * 16];           // per-chunk local max of m
__device__ float g_zl[B_ * 16];           // per-chunk local denominator
__device__ int   g_cnt[B_];               // per-batch completion counters (zero-init; reset by elected CTA)

// ---- smem byte offsets (per-CTA, 64-row m-tile) ----
#define SM_W     0        // 768 f32
#define SM_ROWC  3072     // 64 f32
#define SM_ROWQ  3328     // 128 f32
#define SM_SMAX  3840     // 64x4 f32
#define SM_SSUM  4864     // 64x4 f32
#define SM_SINV  5888     // 64 f32
#define SM_BIAS  6144
#define SM_M     6400     // 64 f32
#define SM_WB    6656     // 64 f32
#define SM_ZML   6912     // 4 f32
#define SM_FLAG  6928     // int: elected flag
#define SM_COEF  6976     // 16 f32
#define SM_DSH   7040     // 1 f32
#define SM_BV    7168     // 256 f32 (ends at 8192)
#define A_OFF    8192     // 4 x 8KB resident fp16 (ctx*w_m) h-chunks (64 rows)
#define AL_OFF   8192     // alpha fp16 [64][128] 16KB, overlays A after GEMM1
#define EPI_OFF  8192     // fp32 a-tile stage [32][260], overlays A+alpha
#define EPI_STR  1040
#define B1_OFF   43008    // 4 x 16KB resident fp16 qry h-chunks
#define SP_OFF   108544   // 4 x 256 f32 s-partial reduction (4KB)
#define SMEM_TOTAL 112640

__device__ __forceinline__ uint32_t smem_u32(const void* p) {
    uint32_t a; asm("{ .reg .u64 t; cvta.to.shared.u64 t, %1; cvt.u32.u64 %0, t; }" : "=r"(a) : "l"(p));
    return a;
}
__device__ __forceinline__ uint32_t pack2(float lo, float hi) {
    uint32_t r; asm("cvt.rn.f16x2.f32 %0, %1, %2;" : "=r"(r) : "f"(hi), "f"(lo)); return r;
}
__device__ __forceinline__ void mma16(float d[4], uint32_t a0, uint32_t a1, uint32_t a2, uint32_t a3,
                                      uint32_t b0, uint32_t b1) {
    asm volatile(
        "mma.sync.aligned.m16n8k16.row.col.f32.f16.f16.f32 "
        "{%0,%1,%2,%3}, {%4,%5,%6,%7}, {%8,%9}, {%0,%1,%2,%3};"
        : "+f"(d[0]), "+f"(d[1]), "+f"(d[2]), "+f"(d[3])
        : "r"(a0), "r"(a1), "r"(a2), "r"(a3), "r"(b0), "r"(b1));
}
#define LDSM4(r0, r1, r2, r3, addr) \
    asm volatile("ldmatrix.sync.aligned.m8n8.x4.shared.b16 {%0,%1,%2,%3}, [%4];" \
        : "=r"(r0), "=r"(r1), "=r"(r2), "=r"(r3) : "r"(addr))
#define LDSM4T(r0, r1, r2, r3, addr) \
    asm volatile("ldmatrix.sync.aligned.m8n8.x4.trans.shared.b16 {%0,%1,%2,%3}, [%4];" \
        : "=r"(r0), "=r"(r1), "=r"(r2), "=r"(r3) : "r"(addr))

// ============================ K1 ============================
__global__ __launch_bounds__(256, 2)
void k1_main(const float* __restrict__ ctx, const float* __restrict__ qry,
             const float* __restrict__ attw, const float* __restrict__ attb,
             float* __restrict__ out)
{
    extern __shared__ __align__(1024) char smem[];
    float* smf = (float*)smem;
    const uint32_t sb = smem_u32(smem);
    const int tid = threadIdx.x, warp = tid >> 5, lane = tid & 31;
    const int mw = warp >> 2, nw = warp & 3;
    const int g = lane >> 3, l7 = lane & 7, gb = g & 1, gh = g >> 1;
    const int b = blockIdx.x >> 3, chalf = blockIdx.x & 7;
    const float* qryb = qry + (size_t)b * Q_ * H_;

    for (int i = tid; i < 768; i += 256) smf[i] = attw[i];
    if (tid == 0) smf[SM_BIAS / 4] = attb[0];
    __syncthreads();

    const float4 wc1 = *(const float4*)(smf + lane * 4);
    const float4 wc2 = *(const float4*)(smf + 128 + lane * 4);
    const float4 wm1 = *(const float4*)(smf + 512 + lane * 4);
    const float4 wm2 = *(const float4*)(smf + 512 + 128 + lane * 4);
    const int j = lane & 15, s1 = lane >> 4;

    // ---- stage qry fp16 (once per CTA) + rowq dots ----
    {
        const float4 wq1 = *(const float4*)(smf + 256 + lane * 4);
        const float4 wq2 = *(const float4*)(smf + 256 + 128 + lane * 4);
        #pragma unroll 4
        for (int i = 0; i < 16; i++) {
            int r = warp * 16 + i;
            float4 q1 = *(const float4*)(qryb + r * H_ + lane * 4);
            float4 q2 = *(const float4*)(qryb + r * H_ + 128 + lane * 4);
            uint32_t off = r * 128 + (((j >> 1) ^ (r & 7)) << 4) + (j & 1) * 8;
            *(uint2*)(smem + B1_OFF + s1 * 16384 + off) =
                make_uint2(pack2(q1.x, q1.y), pack2(q1.z, q1.w));
            *(uint2*)(smem + B1_OFF + (2 + s1) * 16384 + off) =
                make_uint2(pack2(q2.x, q2.y), pack2(q2.z, q2.w));
            float aq = q1.x * wq1.x + q1.y * wq1.y + q1.z * wq1.z + q1.w * wq1.w
                     + q2.x * wq2.x + q2.y * wq2.y + q2.z * wq2.z + q2.w * wq2.w;
            for (int o = 16; o; o >>= 1) aq += __shfl_xor_sync(~0u, aq, o);
            if (lane == 0) smf[SM_ROWQ / 4 + r] = aq;
        }
    }

    for (int cc = 0; cc < 2; cc++) {
        const int ct = chalf * 2 + cc;
        const int chunk_idx = b * 16 + ct;
        const float* ctxb = ctx + ((size_t)(b * C_) + ct * 64) * H_;
        const size_t obase = ((size_t)(b * C_) + ct * 64) * (4 * H_);

        // ---- A0: stage ctx*w_m fp16 (64 rows), rowc dots, out chunk0 = ctx ----
        #pragma unroll 4
        for (int i = 0; i < 8; i++) {
            int r = warp * 8 + i;
            float4 c1 = *(const float4*)(ctxb + r * H_ + lane * 4);
            float4 c2 = *(const float4*)(ctxb + r * H_ + 128 + lane * 4);
            uint32_t off = r * 128 + (((j >> 1) ^ (r & 7)) << 4) + (j & 1) * 8;
            *(uint2*)(smem + A_OFF + s1 * 8192 + off) =
                make_uint2(pack2(c1.x * wm1.x, c1.y * wm1.y), pack2(c1.z * wm1.z, c1.w * wm1.w));
            *(uint2*)(smem + A_OFF + (2 + s1) * 8192 + off) =
                make_uint2(pack2(c2.x * wm2.x, c2.y * wm2.y), pack2(c2.z * wm2.z, c2.w * wm2.w));
            *(float4*)(out + obase + (size_t)r * 1024 + lane * 4) = c1;
            *(float4*)(out + obase + (size_t)r * 1024 + 128 + lane * 4) = c2;
            float ac = c1.x * wc1.x + c1.y * wc1.y + c1.z * wc1.z + c1.w * wc1.w
                     + c2.x * wc2.x + c2.y * wc2.y + c2.z * wc2.z + c2.w * wc2.w;
            for (int o = 16; o; o >>= 1) ac += __shfl_xor_sync(~0u, ac, o);
            if (lane == 0) smf[SM_ROWC / 4 + r] = ac;
        }
        __syncthreads();

        // ---- GEMM1: sim = (ctx*w_m) @ qry^T ; M=64 N=128 K=256, barrier-free ----
        float acc1[2][4][4];
        #pragma unroll
        for (int mt = 0; mt < 2; mt++)
            #pragma unroll
            for (int jj = 0; jj < 4; jj++)
                #pragma unroll
                for (int e = 0; e < 4; e++) acc1[mt][jj][e] = 0.f;

        uint32_t rAb[2], xA[2], rBb[2], xB[2];
        #pragma unroll
        for (int mt = 0; mt < 2; mt++) {
            int row = mw * 32 + mt * 16 + gb * 8 + l7;
            rAb[mt] = row * 128; xA[mt] = row & 7;
        }
        #pragma unroll
        for (int p = 0; p < 2; p++) {
            int row = nw * 32 + p * 16 + gh * 8 + l7;
            rBb[p] = row * 128; xB[p] = row & 7;
        }

        #pragma unroll
        for (int kc = 0; kc < 4; kc++) {
            uint32_t Ab = sb + A_OFF + kc * 8192;
            uint32_t Bb = sb + B1_OFF + kc * 16384;
            #pragma unroll
            for (int ks = 0; ks < 4; ks++) {
                uint32_t a[2][4], bf[2][4];
                #pragma unroll
                for (int mt = 0; mt < 2; mt++) {
                    uint32_t u = 2 * ks + gh;
                    LDSM4(a[mt][0], a[mt][1], a[mt][2], a[mt][3], Ab + rAb[mt] + ((u ^ xA[mt]) << 4));
                }
                #pragma unroll
                for (int p = 0; p < 2; p++) {
                    uint32_t u = 2 * ks + gb;
                    LDSM4(bf[p][0], bf[p][1], bf[p][2], bf[p][3], Bb + rBb[p] + ((u ^ xB[p]) << 4));
                }
                #pragma unroll
                for (int mt = 0; mt < 2; mt++)
                    #pragma unroll
                    for (int p = 0; p < 2; p++) {
                        mma16(acc1[mt][2 * p],     a[mt][0], a[mt][1], a[mt][2], a[mt][3], bf[p][0], bf[p][1]);
                        mma16(acc1[mt][2 * p + 1], a[mt][0], a[mt][1], a[mt][2], a[mt][3], bf[p][2], bf[p][3]);
                    }
            }
        }

        // ---- softmax; alpha fp16 -> AL_OFF (overlays A) ----
        const float* rqv = smf + SM_ROWQ / 4;
        float vmax[4] = { -1e30f, -1e30f, -1e30f, -1e30f };
        #pragma unroll
        for (int mt = 0; mt < 2; mt++)
            #pragma unroll
            for (int jt = 0; jt < 4; jt++) {
                int c0 = nw * 32 + jt * 8 + 2 * (lane & 3);
                float r0 = rqv[c0], r1 = rqv[c0 + 1];
                vmax[2 * mt]     = fmaxf(vmax[2 * mt],     fmaxf(acc1[mt][jt][0] + r0, acc1[mt][jt][1] + r1));
                vmax[2 * mt + 1] = fmaxf(vmax[2 * mt + 1], fmaxf(acc1[mt][jt][2] + r0, acc1[mt][jt][3] + r1));
            }
        #pragma unroll
        for (int r = 0; r < 4; r++) {
            vmax[r] = fmaxf(vmax[r], __shfl_xor_sync(~0u, vmax[r], 1));
            vmax[r] = fmaxf(vmax[r], __shfl_xor_sync(~0u, vmax[r], 2));
        }
        if ((lane & 3) == 0)
            #pragma unroll
            for (int r = 0; r < 4; r++) {
                int row = mw * 32 + (r >> 1) * 16 + (r & 1) * 8 + (lane >> 2);
                smf[SM_SMAX / 4 + row * 4 + nw] = vmax[r];
            }
        __syncthreads();
        float rmax[4], rsum[4] = { 0.f, 0.f, 0.f, 0.f };
        #pragma unroll
        for (int r = 0; r < 4; r++) {
            int row = mw * 32 + (r >> 1) * 16 + (r & 1) * 8 + (lane >> 2);
            float m0 = fmaxf(smf[SM_SMAX / 4 + row * 4],     smf[SM_SMAX / 4 + row * 4 + 1]);
            float m1 = fmaxf(smf[SM_SMAX / 4 + row * 4 + 2], smf[SM_SMAX / 4 + row * 4 + 3]);
            rmax[r] = fmaxf(m0, m1);
        }
        #pragma unroll
        for (int mt = 0; mt < 2; mt++)
            #pragma unroll
            for (int jt = 0; jt < 4; jt++) {
                int c0 = nw * 32 + jt * 8 + 2 * (lane & 3);
                float r0 = rqv[c0], r1 = rqv[c0 + 1];
                float e0 = __expf(acc1[mt][jt][0] + r0 - rmax[2 * mt]);
                float e1 = __expf(acc1[mt][jt][1] + r1 - rmax[2 * mt]);
                float e2 = __expf(acc1[mt][jt][2] + r0 - rmax[2 * mt + 1]);
                float e3 = __expf(acc1[mt][jt][3] + r1 - rmax[2 * mt + 1]);
                rsum[2 * mt] += e0 + e1; rsum[2 * mt + 1] += e2 + e3;
                int rowA = mw * 32 + mt * 16 + (lane >> 2);
                int rowB = rowA + 8;
                int unit = nw * 4 + jt;
                *(uint32_t*)(smem + AL_OFF + rowA * 256 + ((unit ^ (rowA & 7)) << 4) + (lane & 3) * 4)
                    = pack2(e0, e1);
                *(uint32_t*)(smem + AL_OFF + rowB * 256 + ((unit ^ (rowB & 7)) << 4) + (lane & 3) * 4)
                    = pack2(e2, e3);
            }
        #pragma unroll
        for (int r = 0; r < 4; r++) {
            rsum[r] += __shfl_xor_sync(~0u, rsum[r], 1);
            rsum[r] += __shfl_xor_sync(~0u, rsum[r], 2);
        }
        if ((lane & 3) == 0)
            #pragma unroll
            for (int r = 0; r < 4; r++) {
                int row = mw * 32 + (r >> 1) * 16 + (r & 1) * 8 + (lane >> 2);
                smf[SM_SSUM / 4 + row * 4 + nw] = rsum[r];
            }
        __syncthreads();
        if (nw == 0 && (lane & 3) == 0) {
            float bias = smf[SM_BIAS / 4];
            #pragma unroll
            for (int r = 0; r < 4; r++) {
                int row = mw * 32 + (r >> 1) * 16 + (r & 1) * 8 + (lane >> 2);
                float tot = smf[SM_SSUM / 4 + row * 4]     + smf[SM_SSUM / 4 + row * 4 + 1]
                          + smf[SM_SSUM / 4 + row * 4 + 2] + smf[SM_SSUM / 4 + row * 4 + 3];
                smf[SM_SINV / 4 + row] = 1.0f / tot;
                smf[SM_M / 4 + row] = rmax[r] + smf[SM_ROWC / 4 + row] + bias;
            }
        }
        __syncthreads();

        // ---- beta prep: Ml = max m, w = exp(m-Ml), zl = sum w ----
        if (tid < 64) {
            float vm = smf[SM_M / 4 + tid];
            for (int o = 16; o; o >>= 1) vm = fmaxf(vm, __shfl_xor_sync(~0u, vm, o));
            if ((tid & 31) == 0) smf[SM_ZML / 4 + (tid >> 5)] = vm;
        }
        __syncthreads();
        const float Ml = fmaxf(smf[SM_ZML / 4], smf[SM_ZML / 4 + 1]);
        if (tid < 64) {
            float wv = __expf(smf[SM_M / 4 + tid] - Ml);
            smf[SM_WB / 4 + tid] = wv;
            for (int o = 16; o; o >>= 1) wv += __shfl_xor_sync(~0u, wv, o);
            if ((tid & 31) == 0) smf[SM_ZML / 4 + 2 + (tid >> 5)] = wv;
        }
        __syncthreads();
        if (tid == 0) {
            g_Ml[chunk_idx] = Ml;
            g_zl[chunk_idx] = smf[SM_ZML / 4 + 2] + smf[SM_ZML / 4 + 3];
        }

        // ---- GEMM2: D = E @ qry ; M=64, warp n-tile 64 (slot nw), K=128 ----
        float iv[4];
        #pragma unroll
        for (int r = 0; r < 4; r++) {
            int row = mw * 32 + (r >> 1) * 16 + (r & 1) * 8 + (lane >> 2);
            iv[r] = smf[SM_SINV / 4 + row];
        }
        uint32_t rA2b[2], xA2[2];
        #pragma unroll
        for (int mt = 0; mt < 2; mt++) {
            int row = mw * 32 + mt * 16 + gb * 8 + l7;
            rA2b[mt] = row * 256; xA2[mt] = row & 7;
        }
        const uint32_t Bs = sb + B1_OFF + nw * 16384;
        const int qbase = gb * 8 + l7;

        float acc2[8][2][4];
        #pragma unroll
        for (int jj = 0; jj < 8; jj++)
            #pragma unroll
            for (int mt = 0; mt < 2; mt++)
                #pragma unroll
                for (int e = 0; e < 4; e++) acc2[jj][mt][e] = 0.f;

        #pragma unroll
        for (int s = 0; s < 8; s++) {
            uint32_t a[2][4];
            #pragma unroll
            for (int mt = 0; mt < 2; mt++) {
                uint32_t u = 2 * s + gh;
                LDSM4(a[mt][0], a[mt][1], a[mt][2], a[mt][3],
                      sb + AL_OFF + rA2b[mt] + ((u ^ xA2[mt]) << 4));
            }
            uint32_t bt[4][4];
            uint32_t qrow = (uint32_t)(s * 16 + qbase);
            #pragma unroll
            for (int t = 0; t < 4; t++) {
                uint32_t u = 2 * t + gh;
                LDSM4T(bt[t][0], bt[t][1], bt[t][2], bt[t][3],
                       Bs + qrow * 128 + ((u ^ (uint32_t)l7) << 4));
            }
            #pragma unroll
            for (int mt = 0; mt < 2; mt++)
                #pragma unroll
                for (int t = 0; t < 4; t++) {
                    mma16(acc2[2 * t][mt],     a[mt][0], a[mt][1], a[mt][2], a[mt][3], bt[t][0], bt[t][1]);
                    mma16(acc2[2 * t + 1][mt], a[mt][0], a[mt][1], a[mt][2], a[mt][3], bt[t][2], bt[t][3]);
                }
        }
        __syncthreads();   // all GEMM2 alpha reads done before EPI overwrite

        // ---- epilogue: stage a-tile per 32-row half, drain coalesced,
        //      accumulate beta-weighted ctx partials (s_l) on the fly ----
        float sacc[4] = { 0.f, 0.f, 0.f, 0.f };
        #pragma unroll
        for (int p = 0; p < 2; p++) {
            if (mw == p) {
                #pragma unroll
                for (int mt = 0; mt < 2; mt++)
                    #pragma unroll
                    for (int h = 0; h < 2; h++) {
                        int rl = mt * 16 + h * 8 + (lane >> 2);
                        float ivr = iv[mt * 2 + h];
                        #pragma unroll
                        for (int jj = 0; jj < 8; jj++) {
                            int col = nw * 64 + jj * 8 + 2 * (lane & 3);
                            *(float2*)(smem + EPI_OFF + rl * EPI_STR + col * 4) =
                                make_float2(acc2[jj][mt][2 * h] * ivr,
                                            acc2[jj][mt][2 * h + 1] * ivr);
                        }
                    }
            }
            __syncthreads();
            #pragma unroll
            for (int i = 0; i < 8; i++) {
                int idx = i * 256 + tid;
                int rl = idx >> 6, c4 = (idx & 63) * 4;
                float4 av = *(const float4*)(smem + EPI_OFF + rl * EPI_STR + c4 * 4);
                int row = p * 32 + rl;
                float4 cv = *(const float4*)(ctxb + row * 256 + c4);
                float wr = smf[SM_WB / 4 + row];
                sacc[0] += wr * cv.x; sacc[1] += wr * cv.y;
                sacc[2] += wr * cv.z; sacc[3] += wr * cv.w;
                float* o = out + obase + (size_t)row * 1024 + c4;
                *(float4*)(o + 256) = av;
                *(float4*)(o + 512) = make_float4(cv.x * av.x, cv.y * av.y,
                                                  cv.z * av.z, cv.w * av.w);
            }
            __syncthreads();
        }
        // reduce s partials: 4 row-groups x 256 cols
        *(float4*)(smem + SP_OFF + (tid >> 6) * 1024 + (tid & 63) * 16) =
            make_float4(sacc[0], sacc[1], sacc[2], sacc[3]);
        __syncthreads();
        {
            float s = *(const float*)(smem + SP_OFF + tid * 4)
                    + *(const float*)(smem + SP_OFF + 1024 + tid * 4)
                    + *(const float*)(smem + SP_OFF + 2048 + tid * 4)
                    + *(const float*)(smem + SP_OFF + 3072 + tid * 4);
            g_spart[(size_t)chunk_idx * 256 + tid] = s;
        }
        __syncthreads();
    }

    // ======== fused K3 tail: last CTA of batch combines + writes out3 ========
    __threadfence();                       // release g_spart/g_Ml/g_zl writes
    if (tid == 0) {
        int r = atomicAdd(&g_cnt[b], 1);
        *(int*)(smem + SM_FLAG) = (r == 7) ? 1 : 0;
    }
    __syncthreads();
    if (*(int*)(smem + SM_FLAG)) {
        __threadfence();                   // acquire other CTAs' writes
        if (tid < 32) {
            float ml = (tid < 16) ? g_Ml[b * 16 + tid] : -1e30f;
            float M = ml;
            for (int o = 8; o; o >>= 1) M = fmaxf(M, __shfl_xor_sync(~0u, M, o));
            M = __shfl_sync(~0u, M, 0);
            float cf = (tid < 16) ? __expf(ml - M) : 0.f;
            if (tid < 16) smf[SM_COEF / 4 + tid] = cf;
            float dz = (tid < 16) ? cf * g_zl[b * 16 + tid] : 0.f;
            for (int o = 8; o; o >>= 1) dz += __shfl_xor_sync(~0u, dz, o);
            if (tid == 0) smf[SM_DSH / 4] = dz;
        }
        __syncthreads();
        {
            float acc = 0.f;
            #pragma unroll
            for (int l = 0; l < 16; l++)
                acc += smf[SM_COEF / 4 + l] * g_spart[(size_t)(b * 16 + l) * 256 + tid];
            smf[SM_BV / 4 + tid] = acc / smf[SM_DSH / 4];
        }
        __syncthreads();
        const float* cb = ctx + (size_t)b * C_ * H_;
        float* ob = out + (size_t)b * C_ * 1024 + 768;
        #pragma unroll 4
        for (int i = 0; i < 256; i++) {
            int f = i * 256 + tid;
            int row = f >> 6, c4 = (f & 63) * 4;
            float4 cv = *(const float4*)(cb + (size_t)row * 256 + c4);
            float4 bb = *(const float4*)(smf + SM_BV / 4 + c4);
            *(float4*)(ob + (size_t)row * 1024 + c4) =
                make_float4(cv.x * bb.x, cv.y * bb.y, cv.z * bb.z, cv.w * bb.w);
        }
        if (tid == 0) g_cnt[b] = 0;        // reset for next graph replay
    }
}

extern "C" void kernel_launch(void* const* d_in, const int* in_sizes, int n_in,
                              void* d_out, int out_size)
{
    const float* ctx  = (const float*)d_in[0];
    const float* qry  = (const float*)d_in[2];
    const float* attw = (const float*)d_in[4];
    const float* attb = (const float*)d_in[5];
    float* out = (float*)d_out;

    cudaFuncSetAttribute(k1_main, cudaFuncAttributeMaxDynamicSharedMemorySize, SMEM_TOTAL);
    k1_main<<<512, 256, SMEM_TOTAL>>>(ctx, qry, attw, attb, out);
}

// round 15
// speedup vs baseline: 1.3484x; 1.3484x over previous
#include <cuda_runtime.h>
#include <cstdint>

#define B_ 64
#define C_ 1024
#define Q_ 128
#define H_ 256

// ---- scratch ----
__device__ float g_spart[B_ * 16 * H_];   // per-chunk beta-weighted ctx partial sums
__device__ float g_Ml[B_ * 16];           // per-chunk local max of m
__device__ float g_zl[B_ * 16];           // per-chunk local denominator

// ---- smem byte offsets (per-CTA, 64-row m-tile) ----
#define SM_W     0        // 768 f32
#define SM_ROWC  3072     // 64 f32
#define SM_ROWQ  3328     // 128 f32
#define SM_SMAX  3840     // 64x4 f32
#define SM_SSUM  4864     // 64x4 f32
#define SM_SINV  5888     // 64 f32
#define SM_BIAS  6144
#define SM_M     6400     // 64 f32
#define SM_WB    6656     // 64 f32
#define SM_ZML   6912     // 4 f32
#define A_OFF    8192     // 4 x 8KB resident fp16 (ctx*w_m) h-chunks (64 rows)
#define AL_OFF   8192     // alpha fp16 [64][128] 16KB, overlays A after GEMM1
#define EPI_OFF  8192     // fp32 a-tile stage [32][260], overlays A+alpha
#define EPI_STR  1040
#define B1_OFF   43008    // 4 x 16KB resident fp16 qry h-chunks
#define SP_OFF   108544   // 4 x 256 f32 s-partial reduction (4KB)
#define SMEM_TOTAL 112640

__device__ __forceinline__ uint32_t smem_u32(const void* p) {
    uint32_t a; asm("{ .reg .u64 t; cvta.to.shared.u64 t, %1; cvt.u32.u64 %0, t; }" : "=r"(a) : "l"(p));
    return a;
}
__device__ __forceinline__ uint32_t pack2(float lo, float hi) {
    uint32_t r; asm("cvt.rn.f16x2.f32 %0, %1, %2;" : "=r"(r) : "f"(hi), "f"(lo)); return r;
}
__device__ __forceinline__ void mma16(float d[4], uint32_t a0, uint32_t a1, uint32_t a2, uint32_t a3,
                                      uint32_t b0, uint32_t b1) {
    asm volatile(
        "mma.sync.aligned.m16n8k16.row.col.f32.f16.f16.f32 "
        "{%0,%1,%2,%3}, {%4,%5,%6,%7}, {%8,%9}, {%0,%1,%2,%3};"
        : "+f"(d[0]), "+f"(d[1]), "+f"(d[2]), "+f"(d[3])
        : "r"(a0), "r"(a1), "r"(a2), "r"(a3), "r"(b0), "r"(b1));
}
#define LDSM4(r0, r1, r2, r3, addr) \
    asm volatile("ldmatrix.sync.aligned.m8n8.x4.shared.b16 {%0,%1,%2,%3}, [%4];" \
        : "=r"(r0), "=r"(r1), "=r"(r2), "=r"(r3) : "r"(addr))
#define LDSM4T(r0, r1, r2, r3, addr) \
    asm volatile("ldmatrix.sync.aligned.m8n8.x4.trans.shared.b16 {%0,%1,%2,%3}, [%4];" \
        : "=r"(r0), "=r"(r1), "=r"(r2), "=r"(r3) : "r"(addr))

// ============================ K1 ============================
__global__ __launch_bounds__(256, 2)
void k1_main(const float* __restrict__ ctx, const float* __restrict__ qry,
             const float* __restrict__ attw, const float* __restrict__ attb,
             float* __restrict__ out)
{
    extern __shared__ __align__(1024) char smem[];
    float* smf = (float*)smem;
    const uint32_t sb = smem_u32(smem);
    const int tid = threadIdx.x, warp = tid >> 5, lane = tid & 31;
    const int mw = warp >> 2, nw = warp & 3;
    const int g = lane >> 3, l7 = lane & 7, gb = g & 1, gh = g >> 1;
    const int b = blockIdx.x >> 3, chalf = blockIdx.x & 7;
    const float* qryb = qry + (size_t)b * Q_ * H_;

    for (int i = tid; i < 768; i += 256) smf[i] = attw[i];
    if (tid == 0) smf[SM_BIAS / 4] = attb[0];
    __syncthreads();

    const float4 wc1 = *(const float4*)(smf + lane * 4);
    const float4 wc2 = *(const float4*)(smf + 128 + lane * 4);
    const float4 wm1 = *(const float4*)(smf + 512 + lane * 4);
    const float4 wm2 = *(const float4*)(smf + 512 + 128 + lane * 4);
    const int j = lane & 15, s1 = lane >> 4;

    // ---- stage qry fp16 (once per CTA) + rowq dots ----
    {
        const float4 wq1 = *(const float4*)(smf + 256 + lane * 4);
        const float4 wq2 = *(const float4*)(smf + 256 + 128 + lane * 4);
        #pragma unroll 4
        for (int i = 0; i < 16; i++) {
            int r = warp * 16 + i;
            float4 q1 = *(const float4*)(qryb + r * H_ + lane * 4);
            float4 q2 = *(const float4*)(qryb + r * H_ + 128 + lane * 4);
            uint32_t off = r * 128 + (((j >> 1) ^ (r & 7)) << 4) + (j & 1) * 8;
            *(uint2*)(smem + B1_OFF + s1 * 16384 + off) =
                make_uint2(pack2(q1.x, q1.y), pack2(q1.z, q1.w));
            *(uint2*)(smem + B1_OFF + (2 + s1) * 16384 + off) =
                make_uint2(pack2(q2.x, q2.y), pack2(q2.z, q2.w));
            float aq = q1.x * wq1.x + q1.y * wq1.y + q1.z * wq1.z + q1.w * wq1.w
                     + q2.x * wq2.x + q2.y * wq2.y + q2.z * wq2.z + q2.w * wq2.w;
            for (int o = 16; o; o >>= 1) aq += __shfl_xor_sync(~0u, aq, o);
            if (lane == 0) smf[SM_ROWQ / 4 + r] = aq;
        }
    }

    for (int cc = 0; cc < 2; cc++) {
        const int ct = chalf * 2 + cc;
        const int chunk_idx = b * 16 + ct;
        const float* ctxb = ctx + ((size_t)(b * C_) + ct * 64) * H_;
        const size_t obase = ((size_t)(b * C_) + ct * 64) * (4 * H_);

        // ---- A0: stage ctx*w_m fp16 (64 rows), rowc dots, out chunk0 = ctx ----
        #pragma unroll 4
        for (int i = 0; i < 8; i++) {
            int r = warp * 8 + i;
            float4 c1 = *(const float4*)(ctxb + r * H_ + lane * 4);
            float4 c2 = *(const float4*)(ctxb + r * H_ + 128 + lane * 4);
            uint32_t off = r * 128 + (((j >> 1) ^ (r & 7)) << 4) + (j & 1) * 8;
            *(uint2*)(smem + A_OFF + s1 * 8192 + off) =
                make_uint2(pack2(c1.x * wm1.x, c1.y * wm1.y), pack2(c1.z * wm1.z, c1.w * wm1.w));
            *(uint2*)(smem + A_OFF + (2 + s1) * 8192 + off) =
                make_uint2(pack2(c2.x * wm2.x, c2.y * wm2.y), pack2(c2.z * wm2.z, c2.w * wm2.w));
            __stcs((float4*)(out + obase + (size_t)r * 1024 + lane * 4), c1);
            __stcs((float4*)(out + obase + (size_t)r * 1024 + 128 + lane * 4), c2);
            float ac = c1.x * wc1.x + c1.y * wc1.y + c1.z * wc1.z + c1.w * wc1.w
                     + c2.x * wc2.x + c2.y * wc2.y + c2.z * wc2.z + c2.w * wc2.w;
            for (int o = 16; o; o >>= 1) ac += __shfl_xor_sync(~0u, ac, o);
            if (lane == 0) smf[SM_ROWC / 4 + r] = ac;
        }
        __syncthreads();

        // ---- GEMM1: sim = (ctx*w_m) @ qry^T ; M=64 N=128 K=256, barrier-free ----
        float acc1[2][4][4];
        #pragma unroll
        for (int mt = 0; mt < 2; mt++)
            #pragma unroll
            for (int jj = 0; jj < 4; jj++)
                #pragma unroll
                for (int e = 0; e < 4; e++) acc1[mt][jj][e] = 0.f;

        uint32_t rAb[2], xA[2], rBb[2], xB[2];
        #pragma unroll
        for (int mt = 0; mt < 2; mt++) {
            int row = mw * 32 + mt * 16 + gb * 8 + l7;
            rAb[mt] = row * 128; xA[mt] = row & 7;
        }
        #pragma unroll
        for (int p = 0; p < 2; p++) {
            int row = nw * 32 + p * 16 + gh * 8 + l7;
            rBb[p] = row * 128; xB[p] = row & 7;
        }

        #pragma unroll
        for (int kc = 0; kc < 4; kc++) {
            uint32_t Ab = sb + A_OFF + kc * 8192;
            uint32_t Bb = sb + B1_OFF + kc * 16384;
            #pragma unroll
            for (int ks = 0; ks < 4; ks++) {
                uint32_t a[2][4], bf[2][4];
                #pragma unroll
                for (int mt = 0; mt < 2; mt++) {
                    uint32_t u = 2 * ks + gh;
                    LDSM4(a[mt][0], a[mt][1], a[mt][2], a[mt][3], Ab + rAb[mt] + ((u ^ xA[mt]) << 4));
                }
                #pragma unroll
                for (int p = 0; p < 2; p++) {
                    uint32_t u = 2 * ks + gb;
                    LDSM4(bf[p][0], bf[p][1], bf[p][2], bf[p][3], Bb + rBb[p] + ((u ^ xB[p]) << 4));
                }
                #pragma unroll
                for (int mt = 0; mt < 2; mt++)
                    #pragma unroll
                    for (int p = 0; p < 2; p++) {
                        mma16(acc1[mt][2 * p],     a[mt][0], a[mt][1], a[mt][2], a[mt][3], bf[p][0], bf[p][1]);
                        mma16(acc1[mt][2 * p + 1], a[mt][0], a[mt][1], a[mt][2], a[mt][3], bf[p][2], bf[p][3]);
                    }
            }
        }

        // ---- softmax; alpha fp16 -> AL_OFF (overlays A) ----
        const float* rqv = smf + SM_ROWQ / 4;
        float vmax[4] = { -1e30f, -1e30f, -1e30f, -1e30f };
        #pragma unroll
        for (int mt = 0; mt < 2; mt++)
            #pragma unroll
            for (int jt = 0; jt < 4; jt++) {
                int c0 = nw * 32 + jt * 8 + 2 * (lane & 3);
                float r0 = rqv[c0], r1 = rqv[c0 + 1];
                vmax[2 * mt]     = fmaxf(vmax[2 * mt],     fmaxf(acc1[mt][jt][0] + r0, acc1[mt][jt][1] + r1));
                vmax[2 * mt + 1] = fmaxf(vmax[2 * mt + 1], fmaxf(acc1[mt][jt][2] + r0, acc1[mt][jt][3] + r1));
            }
        #pragma unroll
        for (int r = 0; r < 4; r++) {
            vmax[r] = fmaxf(vmax[r], __shfl_xor_sync(~0u, vmax[r], 1));
            vmax[r] = fmaxf(vmax[r], __shfl_xor_sync(~0u, vmax[r], 2));
        }
        if ((lane & 3) == 0)
            #pragma unroll
            for (int r = 0; r < 4; r++) {
                int row = mw * 32 + (r >> 1) * 16 + (r & 1) * 8 + (lane >> 2);
                smf[SM_SMAX / 4 + row * 4 + nw] = vmax[r];
            }
        __syncthreads();
        float rmax[4], rsum[4] = { 0.f, 0.f, 0.f, 0.f };
        #pragma unroll
        for (int r = 0; r < 4; r++) {
            int row = mw * 32 + (r >> 1) * 16 + (r & 1) * 8 + (lane >> 2);
            float m0 = fmaxf(smf[SM_SMAX / 4 + row * 4],     smf[SM_SMAX / 4 + row * 4 + 1]);
            float m1 = fmaxf(smf[SM_SMAX / 4 + row * 4 + 2], smf[SM_SMAX / 4 + row * 4 + 3]);
            rmax[r] = fmaxf(m0, m1);
        }
        #pragma unroll
        for (int mt = 0; mt < 2; mt++)
            #pragma unroll
            for (int jt = 0; jt < 4; jt++) {
                int c0 = nw * 32 + jt * 8 + 2 * (lane & 3);
                float r0 = rqv[c0], r1 = rqv[c0 + 1];
                float e0 = __expf(acc1[mt][jt][0] + r0 - rmax[2 * mt]);
                float e1 = __expf(acc1[mt][jt][1] + r1 - rmax[2 * mt]);
                float e2 = __expf(acc1[mt][jt][2] + r0 - rmax[2 * mt + 1]);
                float e3 = __expf(acc1[mt][jt][3] + r1 - rmax[2 * mt + 1]);
                rsum[2 * mt] += e0 + e1; rsum[2 * mt + 1] += e2 + e3;
                int rowA = mw * 32 + mt * 16 + (lane >> 2);
                int rowB = rowA + 8;
                int unit = nw * 4 + jt;
                *(uint32_t*)(smem + AL_OFF + rowA * 256 + ((unit ^ (rowA & 7)) << 4) + (lane & 3) * 4)
                    = pack2(e0, e1);
                *(uint32_t*)(smem + AL_OFF + rowB * 256 + ((unit ^ (rowB & 7)) << 4) + (lane & 3) * 4)
                    = pack2(e2, e3);
            }
        #pragma unroll
        for (int r = 0; r < 4; r++) {
            rsum[r] += __shfl_xor_sync(~0u, rsum[r], 1);
            rsum[r] += __shfl_xor_sync(~0u, rsum[r], 2);
        }
        if ((lane & 3) == 0)
            #pragma unroll
            for (int r = 0; r < 4; r++) {
                int row = mw * 32 + (r >> 1) * 16 + (r & 1) * 8 + (lane >> 2);
                smf[SM_SSUM / 4 + row * 4 + nw] = rsum[r];
            }
        __syncthreads();
        if (nw == 0 && (lane & 3) == 0) {
            float bias = smf[SM_BIAS / 4];
            #pragma unroll
            for (int r = 0; r < 4; r++) {
                int row = mw * 32 + (r >> 1) * 16 + (r & 1) * 8 + (lane >> 2);
                float tot = smf[SM_SSUM / 4 + row * 4]     + smf[SM_SSUM / 4 + row * 4 + 1]
                          + smf[SM_SSUM / 4 + row * 4 + 2] + smf[SM_SSUM / 4 + row * 4 + 3];
                smf[SM_SINV / 4 + row] = 1.0f / tot;
                smf[SM_M / 4 + row] = rmax[r] + smf[SM_ROWC / 4 + row] + bias;
            }
        }
        __syncthreads();

        // ---- beta prep: Ml = max m, w = exp(m-Ml), zl = sum w ----
        if (tid < 64) {
            float vm = smf[SM_M / 4 + tid];
            for (int o = 16; o; o >>= 1) vm = fmaxf(vm, __shfl_xor_sync(~0u, vm, o));
            if ((tid & 31) == 0) smf[SM_ZML / 4 + (tid >> 5)] = vm;
        }
        __syncthreads();
        const float Ml = fmaxf(smf[SM_ZML / 4], smf[SM_ZML / 4 + 1]);
        if (tid < 64) {
            float wv = __expf(smf[SM_M / 4 + tid] - Ml);
            smf[SM_WB / 4 + tid] = wv;
            for (int o = 16; o; o >>= 1) wv += __shfl_xor_sync(~0u, wv, o);
            if ((tid & 31) == 0) smf[SM_ZML / 4 + 2 + (tid >> 5)] = wv;
        }
        __syncthreads();
        if (tid == 0) {
            g_Ml[chunk_idx] = Ml;
            g_zl[chunk_idx] = smf[SM_ZML / 4 + 2] + smf[SM_ZML / 4 + 3];
        }

        // ---- GEMM2: D = E @ qry ; M=64, warp n-tile 64 (slot nw), K=128 ----
        float iv[4];
        #pragma unroll
        for (int r = 0; r < 4; r++) {
            int row = mw * 32 + (r >> 1) * 16 + (r & 1) * 8 + (lane >> 2);
            iv[r] = smf[SM_SINV / 4 + row];
        }
        uint32_t rA2b[2], xA2[2];
        #pragma unroll
        for (int mt = 0; mt < 2; mt++) {
            int row = mw * 32 + mt * 16 + gb * 8 + l7;
            rA2b[mt] = row * 256; xA2[mt] = row & 7;
        }
        const uint32_t Bs = sb + B1_OFF + nw * 16384;
        const int qbase = gb * 8 + l7;

        float acc2[8][2][4];
        #pragma unroll
        for (int jj = 0; jj < 8; jj++)
            #pragma unroll
            for (int mt = 0; mt < 2; mt++)
                #pragma unroll
                for (int e = 0; e < 4; e++) acc2[jj][mt][e] = 0.f;

        #pragma unroll
        for (int s = 0; s < 8; s++) {
            uint32_t a[2][4];
            #pragma unroll
            for (int mt = 0; mt < 2; mt++) {
                uint32_t u = 2 * s + gh;
                LDSM4(a[mt][0], a[mt][1], a[mt][2], a[mt][3],
                      sb + AL_OFF + rA2b[mt] + ((u ^ xA2[mt]) << 4));
            }
            uint32_t bt[4][4];
            uint32_t qrow = (uint32_t)(s * 16 + qbase);
            #pragma unroll
            for (int t = 0; t < 4; t++) {
                uint32_t u = 2 * t + gh;
                LDSM4T(bt[t][0], bt[t][1], bt[t][2], bt[t][3],
                       Bs + qrow * 128 + ((u ^ (uint32_t)l7) << 4));
            }
            #pragma unroll
            for (int mt = 0; mt < 2; mt++)
                #pragma unroll
                for (int t = 0; t < 4; t++) {
                    mma16(acc2[2 * t][mt],     a[mt][0], a[mt][1], a[mt][2], a[mt][3], bt[t][0], bt[t][1]);
                    mma16(acc2[2 * t + 1][mt], a[mt][0], a[mt][1], a[mt][2], a[mt][3], bt[t][2], bt[t][3]);
                }
        }
        __syncthreads();   // all GEMM2 alpha reads done before EPI overwrite

        // ---- epilogue: stage a-tile per 32-row half, drain coalesced,
        //      accumulate beta-weighted ctx partials (s_l) on the fly ----
        float sacc[4] = { 0.f, 0.f, 0.f, 0.f };
        #pragma unroll
        for (int p = 0; p < 2; p++) {
            if (mw == p) {
                #pragma unroll
                for (int mt = 0; mt < 2; mt++)
                    #pragma unroll
                    for (int h = 0; h < 2; h++) {
                        int rl = mt * 16 + h * 8 + (lane >> 2);
                        float ivr = iv[mt * 2 + h];
                        #pragma unroll
                        for (int jj = 0; jj < 8; jj++) {
                            int col = nw * 64 + jj * 8 + 2 * (lane & 3);
                            *(float2*)(smem + EPI_OFF + rl * EPI_STR + col * 4) =
                                make_float2(acc2[jj][mt][2 * h] * ivr,
                                            acc2[jj][mt][2 * h + 1] * ivr);
                        }
                    }
            }
            __syncthreads();
            #pragma unroll
            for (int i = 0; i < 8; i++) {
                int idx = i * 256 + tid;
                int rl = idx >> 6, c4 = (idx & 63) * 4;
                float4 av = *(const float4*)(smem + EPI_OFF + rl * EPI_STR + c4 * 4);
                int row = p * 32 + rl;
                float4 cv = *(const float4*)(ctxb + row * 256 + c4);
                float wr = smf[SM_WB / 4 + row];
                sacc[0] += wr * cv.x; sacc[1] += wr * cv.y;
                sacc[2] += wr * cv.z; sacc[3] += wr * cv.w;
                float* o = out + obase + (size_t)row * 1024 + c4;
                __stcs((float4*)(o + 256), av);
                __stcs((float4*)(o + 512), make_float4(cv.x * av.x, cv.y * av.y,
                                                       cv.z * av.z, cv.w * av.w));
            }
            __syncthreads();
        }
        // reduce s partials: 4 row-groups x 256 cols
        *(float4*)(smem + SP_OFF + (tid >> 6) * 1024 + (tid & 63) * 16) =
            make_float4(sacc[0], sacc[1], sacc[2], sacc[3]);
        __syncthreads();
        {
            float s = *(const float*)(smem + SP_OFF + tid * 4)
                    + *(const float*)(smem + SP_OFF + 1024 + tid * 4)
                    + *(const float*)(smem + SP_OFF + 2048 + tid * 4)
                    + *(const float*)(smem + SP_OFF + 3072 + tid * 4);
            g_spart[(size_t)chunk_idx * 256 + tid] = s;
        }
        __syncthreads();
    }
}

// ============================ K3: combine + out3 ============================
__global__ __launch_bounds__(256, 1)
void k3_cb(const float* __restrict__ ctx, float* __restrict__ out)
{
    __shared__ float coef[16];
    __shared__ float bv[256];
    __shared__ float dsh;
    const int tid = threadIdx.x;
    const int b = blockIdx.x >> 3, ch = blockIdx.x & 7;

    if (tid < 32) {
        float ml = (tid < 16) ? g_Ml[b * 16 + tid] : -1e30f;
        float M = ml;
        for (int o = 8; o; o >>= 1) M = fmaxf(M, __shfl_xor_sync(~0u, M, o));
        M = __shfl_sync(~0u, M, 0);
        float cf = (tid < 16) ? __expf(ml - M) : 0.f;
        if (tid < 16) coef[tid] = cf;
        float dz = (tid < 16) ? cf * g_zl[b * 16 + tid] : 0.f;
        for (int o = 8; o; o >>= 1) dz += __shfl_xor_sync(~0u, dz, o);
        if (tid == 0) dsh = dz;
    }
    __syncthreads();
    {
        float acc = 0.f;
        #pragma unroll
        for (int l = 0; l < 16; l++)
            acc += coef[l] * g_spart[(size_t)(b * 16 + l) * 256 + tid];
        bv[tid] = acc / dsh;
    }
    __syncthreads();
    const float* cb = ctx + ((size_t)b * 1024 + ch * 128) * 256;
    float* ob = out + ((size_t)(b * 1024) + ch * 128) * 1024 + 768;
    #pragma unroll 4
    for (int i = 0; i < 32; i++) {
        int f = i * 256 + tid;
        int row = f >> 6, c4 = (f & 63) * 4;
        float4 cv = __ldcs((const float4*)(cb + row * 256 + c4));
        float4 bb = *(const float4*)(bv + c4);
        __stcs((float4*)(ob + (size_t)row * 1024 + c4),
               make_float4(cv.x * bb.x, cv.y * bb.y, cv.z * bb.z, cv.w * bb.w));
    }
}

extern "C" void kernel_launch(void* const* d_in, const int* in_sizes, int n_in,
                              void* d_out, int out_size)
{
    const float* ctx  = (const float*)d_in[0];
    const float* qry  = (const float*)d_in[2];
    const float* attw = (const float*)d_in[4];
    const float* attb = (const float*)d_in[5];
    float* out = (float*)d_out;

    cudaFuncSetAttribute(k1_main, cudaFuncAttributeMaxDynamicSharedMemorySize, SMEM_TOTAL);
    k1_main<<<512, 256, SMEM_TOTAL>>>(ctx, qry, attw, attb, out);
    k3_cb<<<512, 256>>>(ctx, out);
}

// round 16
// speedup vs baseline: 1.3755x; 1.0201x over previous
#include <cuda_runtime.h>
#include <cstdint>

#define B_ 64
#define C_ 1024
#define Q_ 128
#define H_ 256

// ---- scratch ----
__device__ float g_spart[B_ * 16 * H_];   // per-chunk beta-weighted ctx partial sums
__device__ float g_Ml[B_ * 16];           // per-chunk local max of m
__device__ float g_zl[B_ * 16];           // per-chunk local denominator

// ---- smem byte offsets (per-CTA, 64-row m-tile) ----
#define SM_W     0        // 768 f32
#define SM_ROWC  3072     // 64 f32
#define SM_ROWQ  3328     // 128 f32
#define SM_SMAX  3840     // 64x4 f32
#define SM_SSUM  4864     // 64x4 f32
#define SM_SINV  5888     // 64 f32
#define SM_BIAS  6144
#define SM_M     6400     // 64 f32
#define SM_WB    6656     // 64 f32
#define SM_ZML   6912     // 4 f32
#define A_OFF    8192     // 4 x 8KB resident fp16 (ctx*w_m) h-chunks (64 rows)
#define AL_OFF   8192     // alpha fp16 [64][128] 16KB, overlays A after GEMM1
#define EPI_OFF  8192     // fp32 a-tile stage [32][260], overlays A+alpha
#define EPI_STR  1040
#define B1_OFF   43008    // 4 x 16KB resident fp16 qry h-chunks
#define SP_OFF   108544   // 4 x 256 f32 s-partial reduction (4KB)
#define SMEM_TOTAL 112640

__device__ __forceinline__ uint32_t smem_u32(const void* p) {
    uint32_t a; asm("{ .reg .u64 t; cvta.to.shared.u64 t, %1; cvt.u32.u64 %0, t; }" : "=r"(a) : "l"(p));
    return a;
}
__device__ __forceinline__ uint32_t pack2(float lo, float hi) {
    uint32_t r; asm("cvt.rn.f16x2.f32 %0, %1, %2;" : "=r"(r) : "f"(hi), "f"(lo)); return r;
}
__device__ __forceinline__ void mma16(float d[4], uint32_t a0, uint32_t a1, uint32_t a2, uint32_t a3,
                                      uint32_t b0, uint32_t b1) {
    asm volatile(
        "mma.sync.aligned.m16n8k16.row.col.f32.f16.f16.f32 "
        "{%0,%1,%2,%3}, {%4,%5,%6,%7}, {%8,%9}, {%0,%1,%2,%3};"
        : "+f"(d[0]), "+f"(d[1]), "+f"(d[2]), "+f"(d[3])
        : "r"(a0), "r"(a1), "r"(a2), "r"(a3), "r"(b0), "r"(b1));
}
#define LDSM4(r0, r1, r2, r3, addr) \
    asm volatile("ldmatrix.sync.aligned.m8n8.x4.shared.b16 {%0,%1,%2,%3}, [%4];" \
        : "=r"(r0), "=r"(r1), "=r"(r2), "=r"(r3) : "r"(addr))
#define LDSM4T(r0, r1, r2, r3, addr) \
    asm volatile("ldmatrix.sync.aligned.m8n8.x4.trans.shared.b16 {%0,%1,%2,%3}, [%4];" \
        : "=r"(r0), "=r"(r1), "=r"(r2), "=r"(r3) : "r"(addr))

// ============================ K1 ============================
__global__ __launch_bounds__(256, 2)
void k1_main(const float* __restrict__ ctx, const float* __restrict__ qry,
             const float* __restrict__ attw, const float* __restrict__ attb,
             float* __restrict__ out)
{
    extern __shared__ __align__(1024) char smem[];
    float* smf = (float*)smem;
    const uint32_t sb = smem_u32(smem);
    const int tid = threadIdx.x, warp = tid >> 5, lane = tid & 31;
    const int mw = warp >> 2, nw = warp & 3;
    const int g = lane >> 3, l7 = lane & 7, gb = g & 1, gh = g >> 1;
    const int b = blockIdx.x >> 3, chalf = blockIdx.x & 7;
    const float* qryb = qry + (size_t)b * Q_ * H_;

    for (int i = tid; i < 768; i += 256) smf[i] = attw[i];
    if (tid == 0) smf[SM_BIAS / 4] = attb[0];
    __syncthreads();

    const float4 wc1 = *(const float4*)(smf + lane * 4);
    const float4 wc2 = *(const float4*)(smf + 128 + lane * 4);
    const float4 wm1 = *(const float4*)(smf + 512 + lane * 4);
    const float4 wm2 = *(const float4*)(smf + 512 + 128 + lane * 4);
    const int j = lane & 15, s1 = lane >> 4;

    // ---- stage qry fp16 (once per CTA) + rowq dots ----
    {
        const float4 wq1 = *(const float4*)(smf + 256 + lane * 4);
        const float4 wq2 = *(const float4*)(smf + 256 + 128 + lane * 4);
        #pragma unroll 4
        for (int i = 0; i < 16; i++) {
            int r = warp * 16 + i;
            float4 q1 = *(const float4*)(qryb + r * H_ + lane * 4);
            float4 q2 = *(const float4*)(qryb + r * H_ + 128 + lane * 4);
            uint32_t off = r * 128 + (((j >> 1) ^ (r & 7)) << 4) + (j & 1) * 8;
            *(uint2*)(smem + B1_OFF + s1 * 16384 + off) =
                make_uint2(pack2(q1.x, q1.y), pack2(q1.z, q1.w));
            *(uint2*)(smem + B1_OFF + (2 + s1) * 16384 + off) =
                make_uint2(pack2(q2.x, q2.y), pack2(q2.z, q2.w));
            float aq = q1.x * wq1.x + q1.y * wq1.y + q1.z * wq1.z + q1.w * wq1.w
                     + q2.x * wq2.x + q2.y * wq2.y + q2.z * wq2.z + q2.w * wq2.w;
            for (int o = 16; o; o >>= 1) aq += __shfl_xor_sync(~0u, aq, o);
            if (lane == 0) smf[SM_ROWQ / 4 + r] = aq;
        }
    }

    for (int cc = 0; cc < 2; cc++) {
        const int ct = chalf * 2 + cc;
        const int chunk_idx = b * 16 + ct;
        const float* ctxb = ctx + ((size_t)(b * C_) + ct * 64) * H_;
        const size_t obase = ((size_t)(b * C_) + ct * 64) * (4 * H_);

        // ---- A0: stage ctx*w_m fp16 (64 rows), rowc dots, out chunk0 = ctx ----
        #pragma unroll 4
        for (int i = 0; i < 8; i++) {
            int r = warp * 8 + i;
            float4 c1 = *(const float4*)(ctxb + r * H_ + lane * 4);
            float4 c2 = *(const float4*)(ctxb + r * H_ + 128 + lane * 4);
            uint32_t off = r * 128 + (((j >> 1) ^ (r & 7)) << 4) + (j & 1) * 8;
            *(uint2*)(smem + A_OFF + s1 * 8192 + off) =
                make_uint2(pack2(c1.x * wm1.x, c1.y * wm1.y), pack2(c1.z * wm1.z, c1.w * wm1.w));
            *(uint2*)(smem + A_OFF + (2 + s1) * 8192 + off) =
                make_uint2(pack2(c2.x * wm2.x, c2.y * wm2.y), pack2(c2.z * wm2.z, c2.w * wm2.w));
            __stcs((float4*)(out + obase + (size_t)r * 1024 + lane * 4), c1);
            __stcs((float4*)(out + obase + (size_t)r * 1024 + 128 + lane * 4), c2);
            float ac = c1.x * wc1.x + c1.y * wc1.y + c1.z * wc1.z + c1.w * wc1.w
                     + c2.x * wc2.x + c2.y * wc2.y + c2.z * wc2.z + c2.w * wc2.w;
            for (int o = 16; o; o >>= 1) ac += __shfl_xor_sync(~0u, ac, o);
            if (lane == 0) smf[SM_ROWC / 4 + r] = ac;
        }
        __syncthreads();

        // ---- GEMM1: sim = (ctx*w_m) @ qry^T ; M=64 N=128 K=256, barrier-free ----
        float acc1[2][4][4];
        #pragma unroll
        for (int mt = 0; mt < 2; mt++)
            #pragma unroll
            for (int jj = 0; jj < 4; jj++)
                #pragma unroll
                for (int e = 0; e < 4; e++) acc1[mt][jj][e] = 0.f;

        uint32_t rAb[2], xA[2], rBb[2], xB[2];
        #pragma unroll
        for (int mt = 0; mt < 2; mt++) {
            int row = mw * 32 + mt * 16 + gb * 8 + l7;
            rAb[mt] = row * 128; xA[mt] = row & 7;
        }
        #pragma unroll
        for (int p = 0; p < 2; p++) {
            int row = nw * 32 + p * 16 + gh * 8 + l7;
            rBb[p] = row * 128; xB[p] = row & 7;
        }

        #pragma unroll
        for (int kc = 0; kc < 4; kc++) {
            uint32_t Ab = sb + A_OFF + kc * 8192;
            uint32_t Bb = sb + B1_OFF + kc * 16384;
            #pragma unroll
            for (int ks = 0; ks < 4; ks++) {
                uint32_t a[2][4], bf[2][4];
                #pragma unroll
                for (int mt = 0; mt < 2; mt++) {
                    uint32_t u = 2 * ks + gh;
                    LDSM4(a[mt][0], a[mt][1], a[mt][2], a[mt][3], Ab + rAb[mt] + ((u ^ xA[mt]) << 4));
                }
                #pragma unroll
                for (int p = 0; p < 2; p++) {
                    uint32_t u = 2 * ks + gb;
                    LDSM4(bf[p][0], bf[p][1], bf[p][2], bf[p][3], Bb + rBb[p] + ((u ^ xB[p]) << 4));
                }
                #pragma unroll
                for (int mt = 0; mt < 2; mt++)
                    #pragma unroll
                    for (int p = 0; p < 2; p++) {
                        mma16(acc1[mt][2 * p],     a[mt][0], a[mt][1], a[mt][2], a[mt][3], bf[p][0], bf[p][1]);
                        mma16(acc1[mt][2 * p + 1], a[mt][0], a[mt][1], a[mt][2], a[mt][3], bf[p][2], bf[p][3]);
                    }
            }
        }

        // ---- softmax; alpha fp16 -> AL_OFF (overlays A) ----
        const float* rqv = smf + SM_ROWQ / 4;
        float vmax[4] = { -1e30f, -1e30f, -1e30f, -1e30f };
        #pragma unroll
        for (int mt = 0; mt < 2; mt++)
            #pragma unroll
            for (int jt = 0; jt < 4; jt++) {
                int c0 = nw * 32 + jt * 8 + 2 * (lane & 3);
                float r0 = rqv[c0], r1 = rqv[c0 + 1];
                vmax[2 * mt]     = fmaxf(vmax[2 * mt],     fmaxf(acc1[mt][jt][0] + r0, acc1[mt][jt][1] + r1));
                vmax[2 * mt + 1] = fmaxf(vmax[2 * mt + 1], fmaxf(acc1[mt][jt][2] + r0, acc1[mt][jt][3] + r1));
            }
        #pragma unroll
        for (int r = 0; r < 4; r++) {
            vmax[r] = fmaxf(vmax[r], __shfl_xor_sync(~0u, vmax[r], 1));
            vmax[r] = fmaxf(vmax[r], __shfl_xor_sync(~0u, vmax[r], 2));
        }
        if ((lane & 3) == 0)
            #pragma unroll
            for (int r = 0; r < 4; r++) {
                int row = mw * 32 + (r >> 1) * 16 + (r & 1) * 8 + (lane >> 2);
                smf[SM_SMAX / 4 + row * 4 + nw] = vmax[r];
            }
        __syncthreads();
        float rmax[4], rsum[4] = { 0.f, 0.f, 0.f, 0.f };
        #pragma unroll
        for (int r = 0; r < 4; r++) {
            int row = mw * 32 + (r >> 1) * 16 + (r & 1) * 8 + (lane >> 2);
            float m0 = fmaxf(smf[SM_SMAX / 4 + row * 4],     smf[SM_SMAX / 4 + row * 4 + 1]);
            float m1 = fmaxf(smf[SM_SMAX / 4 + row * 4 + 2], smf[SM_SMAX / 4 + row * 4 + 3]);
            rmax[r] = fmaxf(m0, m1);
        }
        #pragma unroll
        for (int mt = 0; mt < 2; mt++)
            #pragma unroll
            for (int jt = 0; jt < 4; jt++) {
                int c0 = nw * 32 + jt * 8 + 2 * (lane & 3);
                float r0 = rqv[c0], r1 = rqv[c0 + 1];
                float e0 = __expf(acc1[mt][jt][0] + r0 - rmax[2 * mt]);
                float e1 = __expf(acc1[mt][jt][1] + r1 - rmax[2 * mt]);
                float e2 = __expf(acc1[mt][jt][2] + r0 - rmax[2 * mt + 1]);
                float e3 = __expf(acc1[mt][jt][3] + r1 - rmax[2 * mt + 1]);
                rsum[2 * mt] += e0 + e1; rsum[2 * mt + 1] += e2 + e3;
                int rowA = mw * 32 + mt * 16 + (lane >> 2);
                int rowB = rowA + 8;
                int unit = nw * 4 + jt;
                *(uint32_t*)(smem + AL_OFF + rowA * 256 + ((unit ^ (rowA & 7)) << 4) + (lane & 3) * 4)
                    = pack2(e0, e1);
                *(uint32_t*)(smem + AL_OFF + rowB * 256 + ((unit ^ (rowB & 7)) << 4) + (lane & 3) * 4)
                    = pack2(e2, e3);
            }
        #pragma unroll
        for (int r = 0; r < 4; r++) {
            rsum[r] += __shfl_xor_sync(~0u, rsum[r], 1);
            rsum[r] += __shfl_xor_sync(~0u, rsum[r], 2);
        }
        if ((lane & 3) == 0)
            #pragma unroll
            for (int r = 0; r < 4; r++) {
                int row = mw * 32 + (r >> 1) * 16 + (r & 1) * 8 + (lane >> 2);
                smf[SM_SSUM / 4 + row * 4 + nw] = rsum[r];
            }
        __syncthreads();
        if (nw == 0 && (lane & 3) == 0) {
            float bias = smf[SM_BIAS / 4];
            #pragma unroll
            for (int r = 0; r < 4; r++) {
                int row = mw * 32 + (r >> 1) * 16 + (r & 1) * 8 + (lane >> 2);
                float tot = smf[SM_SSUM / 4 + row * 4]     + smf[SM_SSUM / 4 + row * 4 + 1]
                          + smf[SM_SSUM / 4 + row * 4 + 2] + smf[SM_SSUM / 4 + row * 4 + 3];
                smf[SM_SINV / 4 + row] = 1.0f / tot;
                smf[SM_M / 4 + row] = rmax[r] + smf[SM_ROWC / 4 + row] + bias;
            }
        }
        __syncthreads();

        // ---- beta prep: Ml = max m, w = exp(m-Ml), zl = sum w ----
        if (tid < 64) {
            float vm = smf[SM_M / 4 + tid];
            for (int o = 16; o; o >>= 1) vm = fmaxf(vm, __shfl_xor_sync(~0u, vm, o));
            if ((tid & 31) == 0) smf[SM_ZML / 4 + (tid >> 5)] = vm;
        }
        __syncthreads();
        const float Ml = fmaxf(smf[SM_ZML / 4], smf[SM_ZML / 4 + 1]);
        if (tid < 64) {
            float wv = __expf(smf[SM_M / 4 + tid] - Ml);
            smf[SM_WB / 4 + tid] = wv;
            for (int o = 16; o; o >>= 1) wv += __shfl_xor_sync(~0u, wv, o);
            if ((tid & 31) == 0) smf[SM_ZML / 4 + 2 + (tid >> 5)] = wv;
        }
        __syncthreads();
        if (tid == 0) {
            g_Ml[chunk_idx] = Ml;
            g_zl[chunk_idx] = smf[SM_ZML / 4 + 2] + smf[SM_ZML / 4 + 3];
        }

        // ---- GEMM2: D = E @ qry ; M=64, warp n-tile 64 (slot nw), K=128 ----
        float iv[4];
        #pragma unroll
        for (int r = 0; r < 4; r++) {
            int row = mw * 32 + (r >> 1) * 16 + (r & 1) * 8 + (lane >> 2);
            iv[r] = smf[SM_SINV / 4 + row];
        }
        uint32_t rA2b[2], xA2[2];
        #pragma unroll
        for (int mt = 0; mt < 2; mt++) {
            int row = mw * 32 + mt * 16 + gb * 8 + l7;
            rA2b[mt] = row * 256; xA2[mt] = row & 7;
        }
        const uint32_t Bs = sb + B1_OFF + nw * 16384;
        const int qbase = gb * 8 + l7;

        float acc2[8][2][4];
        #pragma unroll
        for (int jj = 0; jj < 8; jj++)
            #pragma unroll
            for (int mt = 0; mt < 2; mt++)
                #pragma unroll
                for (int e = 0; e < 4; e++) acc2[jj][mt][e] = 0.f;

        #pragma unroll
        for (int s = 0; s < 8; s++) {
            uint32_t a[2][4];
            #pragma unroll
            for (int mt = 0; mt < 2; mt++) {
                uint32_t u = 2 * s + gh;
                LDSM4(a[mt][0], a[mt][1], a[mt][2], a[mt][3],
                      sb + AL_OFF + rA2b[mt] + ((u ^ xA2[mt]) << 4));
            }
            uint32_t bt[4][4];
            uint32_t qrow = (uint32_t)(s * 16 + qbase);
            #pragma unroll
            for (int t = 0; t < 4; t++) {
                uint32_t u = 2 * t + gh;
                LDSM4T(bt[t][0], bt[t][1], bt[t][2], bt[t][3],
                       Bs + qrow * 128 + ((u ^ (uint32_t)l7) << 4));
            }
            #pragma unroll
            for (int mt = 0; mt < 2; mt++)
                #pragma unroll
                for (int t = 0; t < 4; t++) {
                    mma16(acc2[2 * t][mt],     a[mt][0], a[mt][1], a[mt][2], a[mt][3], bt[t][0], bt[t][1]);
                    mma16(acc2[2 * t + 1][mt], a[mt][0], a[mt][1], a[mt][2], a[mt][3], bt[t][2], bt[t][3]);
                }
        }
        __syncthreads();   // all GEMM2 alpha reads done before EPI overwrite

        // ---- epilogue: stage a-tile per 32-row half, drain coalesced,
        //      accumulate beta-weighted ctx partials (s_l) on the fly ----
        float sacc[4] = { 0.f, 0.f, 0.f, 0.f };
        #pragma unroll
        for (int p = 0; p < 2; p++) {
            if (mw == p) {
                #pragma unroll
                for (int mt = 0; mt < 2; mt++)
                    #pragma unroll
                    for (int h = 0; h < 2; h++) {
                        int rl = mt * 16 + h * 8 + (lane >> 2);
                        float ivr = iv[mt * 2 + h];
                        #pragma unroll
                        for (int jj = 0; jj < 8; jj++) {
                            int col = nw * 64 + jj * 8 + 2 * (lane & 3);
                            *(float2*)(smem + EPI_OFF + rl * EPI_STR + col * 4) =
                                make_float2(acc2[jj][mt][2 * h] * ivr,
                                            acc2[jj][mt][2 * h + 1] * ivr);
                        }
                    }
            }
            __syncthreads();
            #pragma unroll
            for (int i = 0; i < 8; i++) {
                int idx = i * 256 + tid;
                int rl = idx >> 6, c4 = (idx & 63) * 4;
                float4 av = *(const float4*)(smem + EPI_OFF + rl * EPI_STR + c4 * 4);
                int row = p * 32 + rl;
                float4 cv = *(const float4*)(ctxb + row * 256 + c4);
                float wr = smf[SM_WB / 4 + row];
                sacc[0] += wr * cv.x; sacc[1] += wr * cv.y;
                sacc[2] += wr * cv.z; sacc[3] += wr * cv.w;
                float* o = out + obase + (size_t)row * 1024 + c4;
                __stcs((float4*)(o + 256), av);
                __stcs((float4*)(o + 512), make_float4(cv.x * av.x, cv.y * av.y,
                                                       cv.z * av.z, cv.w * av.w));
            }
            __syncthreads();
        }
        // reduce s partials: 4 row-groups x 256 cols
        *(float4*)(smem + SP_OFF + (tid >> 6) * 1024 + (tid & 63) * 16) =
            make_float4(sacc[0], sacc[1], sacc[2], sacc[3]);
        __syncthreads();
        {
            float s = *(const float*)(smem + SP_OFF + tid * 4)
                    + *(const float*)(smem + SP_OFF + 1024 + tid * 4)
                    + *(const float*)(smem + SP_OFF + 2048 + tid * 4)
                    + *(const float*)(smem + SP_OFF + 3072 + tid * 4);
            g_spart[(size_t)chunk_idx * 256 + tid] = s;
        }
        __syncthreads();
    }
}

// ============================ K3: combine + out3 (32-row slices) ============================
__global__ __launch_bounds__(256, 8)
void k3_cb(const float* __restrict__ ctx, float* __restrict__ out)
{
    __shared__ float coef[16];
    __shared__ float bv[256];
    __shared__ float dsh;
    const int tid = threadIdx.x;
    const int b = blockIdx.x >> 5, ch = blockIdx.x & 31;

    if (tid < 32) {
        float ml = (tid < 16) ? g_Ml[b * 16 + tid] : -1e30f;
        float M = ml;
        for (int o = 8; o; o >>= 1) M = fmaxf(M, __shfl_xor_sync(~0u, M, o));
        M = __shfl_sync(~0u, M, 0);
        float cf = (tid < 16) ? __expf(ml - M) : 0.f;
        if (tid < 16) coef[tid] = cf;
        float dz = (tid < 16) ? cf * g_zl[b * 16 + tid] : 0.f;
        for (int o = 8; o; o >>= 1) dz += __shfl_xor_sync(~0u, dz, o);
        if (tid == 0) dsh = dz;
    }
    __syncthreads();
    {
        float acc = 0.f;
        #pragma unroll
        for (int l = 0; l < 16; l++)
            acc += coef[l] * g_spart[(size_t)(b * 16 + l) * 256 + tid];
        bv[tid] = acc / dsh;
    }
    __syncthreads();
    const float* cb = ctx + ((size_t)b * 1024 + ch * 32) * 256;
    float* ob = out + ((size_t)(b * 1024) + ch * 32) * 1024 + 768;
    #pragma unroll
    for (int i = 0; i < 8; i++) {
        int f = i * 256 + tid;
        int row = f >> 6, c4 = (f & 63) * 4;
        float4 cv = *(const float4*)(cb + row * 256 + c4);
        float4 bb = *(const float4*)(bv + c4);
        __stcs((float4*)(ob + (size_t)row * 1024 + c4),
               make_float4(cv.x * bb.x, cv.y * bb.y, cv.z * bb.z, cv.w * bb.w));
    }
}

extern "C" void kernel_launch(void* const* d_in, const int* in_sizes, int n_in,
                              void* d_out, int out_size)
{
    const float* ctx  = (const float*)d_in[0];
    const float* qry  = (const float*)d_in[2];
    const float* attw = (const float*)d_in[4];
    const float* attb = (const float*)d_in[5];
    float* out = (float*)d_out;

    cudaFuncSetAttribute(k1_main, cudaFuncAttributeMaxDynamicSharedMemorySize, SMEM_TOTAL);
    k1_main<<<512, 256, SMEM_TOTAL>>>(ctx, qry, attw, attb, out);
    k3_cb<<<2048, 256>>>(ctx, out);
}

// round 17
// speedup vs baseline: 1.4445x; 1.0502x over previous
#include <cuda_runtime.h>
#include <cstdint>

#define B_ 64
#define C_ 1024
#define Q_ 128
#define H_ 256

// ---- scratch ----
__device__ float g_spart[B_ * 16 * H_];   // per-chunk beta-weighted ctx partial sums
__device__ float g_Ml[B_ * 16];           // per-chunk local max of m
__device__ float g_zl[B_ * 16];           // per-chunk local denominator
__device__ int   g_cnt[B_];               // per-batch arrival counters (zero-init; self-resetting)

// ---- smem byte offsets (per-CTA, 64-row m-tile) ----
#define SM_W     0        // 768 f32
#define SM_ROWC  3072     // 64 f32
#define SM_ROWQ  3328     // 128 f32
#define SM_SMAX  3840     // 64x4 f32
#define SM_SSUM  4864     // 64x4 f32
#define SM_SINV  5888     // 64 f32
#define SM_BIAS  6144
#define SM_M     6400     // 64 f32
#define SM_WB    6656     // 64 f32
#define SM_ZML   6912     // 4 f32
#define SM_COEF  6976     // 16 f32
#define SM_DSH   7040     // 1 f32
#define SM_BV    7168     // 256 f32 (ends at 8192)
#define A_OFF    8192     // 4 x 8KB resident fp16 (ctx*w_m) h-chunks (64 rows)
#define AL_OFF   8192     // alpha fp16 [64][128] 16KB, overlays A after GEMM1
#define EPI_OFF  8192     // fp32 a-tile stage [32][260], overlays A+alpha
#define EPI_STR  1040
#define B1_OFF   43008    // 4 x 16KB resident fp16 qry h-chunks
#define SP_OFF   108544   // 4 x 256 f32 s-partial reduction (4KB)
#define SMEM_TOTAL 112640

__device__ __forceinline__ uint32_t smem_u32(const void* p) {
    uint32_t a; asm("{ .reg .u64 t; cvta.to.shared.u64 t, %1; cvt.u32.u64 %0, t; }" : "=r"(a) : "l"(p));
    return a;
}
__device__ __forceinline__ uint32_t pack2(float lo, float hi) {
    uint32_t r; asm("cvt.rn.f16x2.f32 %0, %1, %2;" : "=r"(r) : "f"(hi), "f"(lo)); return r;
}
__device__ __forceinline__ void mma16(float d[4], uint32_t a0, uint32_t a1, uint32_t a2, uint32_t a3,
                                      uint32_t b0, uint32_t b1) {
    asm volatile(
        "mma.sync.aligned.m16n8k16.row.col.f32.f16.f16.f32 "
        "{%0,%1,%2,%3}, {%4,%5,%6,%7}, {%8,%9}, {%0,%1,%2,%3};"
        : "+f"(d[0]), "+f"(d[1]), "+f"(d[2]), "+f"(d[3])
        : "r"(a0), "r"(a1), "r"(a2), "r"(a3), "r"(b0), "r"(b1));
}
#define LDSM4(r0, r1, r2, r3, addr) \
    asm volatile("ldmatrix.sync.aligned.m8n8.x4.shared.b16 {%0,%1,%2,%3}, [%4];" \
        : "=r"(r0), "=r"(r1), "=r"(r2), "=r"(r3) : "r"(addr))
#define LDSM4T(r0, r1, r2, r3, addr) \
    asm volatile("ldmatrix.sync.aligned.m8n8.x4.trans.shared.b16 {%0,%1,%2,%3}, [%4];" \
        : "=r"(r0), "=r"(r1), "=r"(r2), "=r"(r3) : "r"(addr))

// ============================ K1 (fused) ============================
__global__ __launch_bounds__(256, 2)
void k1_main(const float* __restrict__ ctx, const float* __restrict__ qry,
             const float* __restrict__ attw, const float* __restrict__ attb,
             float* __restrict__ out)
{
    extern __shared__ __align__(1024) char smem[];
    float* smf = (float*)smem;
    const uint32_t sb = smem_u32(smem);
    const int tid = threadIdx.x, warp = tid >> 5, lane = tid & 31;
    const int mw = warp >> 2, nw = warp & 3;
    const int g = lane >> 3, l7 = lane & 7, gb = g & 1, gh = g >> 1;
    const int b = blockIdx.x >> 3, chalf = blockIdx.x & 7;
    const float* qryb = qry + (size_t)b * Q_ * H_;

    for (int i = tid; i < 768; i += 256) smf[i] = attw[i];
    if (tid == 0) smf[SM_BIAS / 4] = attb[0];
    __syncthreads();

    const float4 wc1 = *(const float4*)(smf + lane * 4);
    const float4 wc2 = *(const float4*)(smf + 128 + lane * 4);
    const float4 wm1 = *(const float4*)(smf + 512 + lane * 4);
    const float4 wm2 = *(const float4*)(smf + 512 + 128 + lane * 4);
    const int j = lane & 15, s1 = lane >> 4;

    // ---- stage qry fp16 (once per CTA) + rowq dots ----
    {
        const float4 wq1 = *(const float4*)(smf + 256 + lane * 4);
        const float4 wq2 = *(const float4*)(smf + 256 + 128 + lane * 4);
        #pragma unroll 4
        for (int i = 0; i < 16; i++) {
            int r = warp * 16 + i;
            float4 q1 = *(const float4*)(qryb + r * H_ + lane * 4);
            float4 q2 = *(const float4*)(qryb + r * H_ + 128 + lane * 4);
            uint32_t off = r * 128 + (((j >> 1) ^ (r & 7)) << 4) + (j & 1) * 8;
            *(uint2*)(smem + B1_OFF + s1 * 16384 + off) =
                make_uint2(pack2(q1.x, q1.y), pack2(q1.z, q1.w));
            *(uint2*)(smem + B1_OFF + (2 + s1) * 16384 + off) =
                make_uint2(pack2(q2.x, q2.y), pack2(q2.z, q2.w));
            float aq = q1.x * wq1.x + q1.y * wq1.y + q1.z * wq1.z + q1.w * wq1.w
                     + q2.x * wq2.x + q2.y * wq2.y + q2.z * wq2.z + q2.w * wq2.w;
            for (int o = 16; o; o >>= 1) aq += __shfl_xor_sync(~0u, aq, o);
            if (lane == 0) smf[SM_ROWQ / 4 + r] = aq;
        }
    }

    for (int cc = 0; cc < 2; cc++) {
        const int ct = chalf * 2 + cc;
        const int chunk_idx = b * 16 + ct;
        const float* ctxb = ctx + ((size_t)(b * C_) + ct * 64) * H_;
        const size_t obase = ((size_t)(b * C_) + ct * 64) * (4 * H_);

        // ---- A0: stage ctx*w_m fp16 (64 rows), rowc dots, out chunk0 = ctx ----
        #pragma unroll 4
        for (int i = 0; i < 8; i++) {
            int r = warp * 8 + i;
            float4 c1 = *(const float4*)(ctxb + r * H_ + lane * 4);
            float4 c2 = *(const float4*)(ctxb + r * H_ + 128 + lane * 4);
            uint32_t off = r * 128 + (((j >> 1) ^ (r & 7)) << 4) + (j & 1) * 8;
            *(uint2*)(smem + A_OFF + s1 * 8192 + off) =
                make_uint2(pack2(c1.x * wm1.x, c1.y * wm1.y), pack2(c1.z * wm1.z, c1.w * wm1.w));
            *(uint2*)(smem + A_OFF + (2 + s1) * 8192 + off) =
                make_uint2(pack2(c2.x * wm2.x, c2.y * wm2.y), pack2(c2.z * wm2.z, c2.w * wm2.w));
            __stcs((float4*)(out + obase + (size_t)r * 1024 + lane * 4), c1);
            __stcs((float4*)(out + obase + (size_t)r * 1024 + 128 + lane * 4), c2);
            float ac = c1.x * wc1.x + c1.y * wc1.y + c1.z * wc1.z + c1.w * wc1.w
                     + c2.x * wc2.x + c2.y * wc2.y + c2.z * wc2.z + c2.w * wc2.w;
            for (int o = 16; o; o >>= 1) ac += __shfl_xor_sync(~0u, ac, o);
            if (lane == 0) smf[SM_ROWC / 4 + r] = ac;
        }
        __syncthreads();

        // ---- GEMM1: sim = (ctx*w_m) @ qry^T ; M=64 N=128 K=256, barrier-free ----
        float acc1[2][4][4];
        #pragma unroll
        for (int mt = 0; mt < 2; mt++)
            #pragma unroll
            for (int jj = 0; jj < 4; jj++)
                #pragma unroll
                for (int e = 0; e < 4; e++) acc1[mt][jj][e] = 0.f;

        uint32_t rAb[2], xA[2], rBb[2], xB[2];
        #pragma unroll
        for (int mt = 0; mt < 2; mt++) {
            int row = mw * 32 + mt * 16 + gb * 8 + l7;
            rAb[mt] = row * 128; xA[mt] = row & 7;
        }
        #pragma unroll
        for (int p = 0; p < 2; p++) {
            int row = nw * 32 + p * 16 + gh * 8 + l7;
            rBb[p] = row * 128; xB[p] = row & 7;
        }

        #pragma unroll
        for (int kc = 0; kc < 4; kc++) {
            uint32_t Ab = sb + A_OFF + kc * 8192;
            uint32_t Bb = sb + B1_OFF + kc * 16384;
            #pragma unroll
            for (int ks = 0; ks < 4; ks++) {
                uint32_t a[2][4], bf[2][4];
                #pragma unroll
                for (int mt = 0; mt < 2; mt++) {
                    uint32_t u = 2 * ks + gh;
                    LDSM4(a[mt][0], a[mt][1], a[mt][2], a[mt][3], Ab + rAb[mt] + ((u ^ xA[mt]) << 4));
                }
                #pragma unroll
                for (int p = 0; p < 2; p++) {
                    uint32_t u = 2 * ks + gb;
                    LDSM4(bf[p][0], bf[p][1], bf[p][2], bf[p][3], Bb + rBb[p] + ((u ^ xB[p]) << 4));
                }
                #pragma unroll
                for (int mt = 0; mt < 2; mt++)
                    #pragma unroll
                    for (int p = 0; p < 2; p++) {
                        mma16(acc1[mt][2 * p],     a[mt][0], a[mt][1], a[mt][2], a[mt][3], bf[p][0], bf[p][1]);
                        mma16(acc1[mt][2 * p + 1], a[mt][0], a[mt][1], a[mt][2], a[mt][3], bf[p][2], bf[p][3]);
                    }
            }
        }

        // ---- softmax; alpha fp16 -> AL_OFF (overlays A) ----
        const float* rqv = smf + SM_ROWQ / 4;
        float vmax[4] = { -1e30f, -1e30f, -1e30f, -1e30f };
        #pragma unroll
        for (int mt = 0; mt < 2; mt++)
            #pragma unroll
            for (int jt = 0; jt < 4; jt++) {
                int c0 = nw * 32 + jt * 8 + 2 * (lane & 3);
                float r0 = rqv[c0], r1 = rqv[c0 + 1];
                vmax[2 * mt]     = fmaxf(vmax[2 * mt],     fmaxf(acc1[mt][jt][0] + r0, acc1[mt][jt][1] + r1));
                vmax[2 * mt + 1] = fmaxf(vmax[2 * mt + 1], fmaxf(acc1[mt][jt][2] + r0, acc1[mt][jt][3] + r1));
            }
        #pragma unroll
        for (int r = 0; r < 4; r++) {
            vmax[r] = fmaxf(vmax[r], __shfl_xor_sync(~0u, vmax[r], 1));
            vmax[r] = fmaxf(vmax[r], __shfl_xor_sync(~0u, vmax[r], 2));
        }
        if ((lane & 3) == 0)
            #pragma unroll
            for (int r = 0; r < 4; r++) {
                int row = mw * 32 + (r >> 1) * 16 + (r & 1) * 8 + (lane >> 2);
                smf[SM_SMAX / 4 + row * 4 + nw] = vmax[r];
            }
        __syncthreads();
        float rmax[4], rsum[4] = { 0.f, 0.f, 0.f, 0.f };
        #pragma unroll
        for (int r = 0; r < 4; r++) {
            int row = mw * 32 + (r >> 1) * 16 + (r & 1) * 8 + (lane >> 2);
            float m0 = fmaxf(smf[SM_SMAX / 4 + row * 4],     smf[SM_SMAX / 4 + row * 4 + 1]);
            float m1 = fmaxf(smf[SM_SMAX / 4 + row * 4 + 2], smf[SM_SMAX / 4 + row * 4 + 3]);
            rmax[r] = fmaxf(m0, m1);
        }
        #pragma unroll
        for (int mt = 0; mt < 2; mt++)
            #pragma unroll
            for (int jt = 0; jt < 4; jt++) {
                int c0 = nw * 32 + jt * 8 + 2 * (lane & 3);
                float r0 = rqv[c0], r1 = rqv[c0 + 1];
                float e0 = __expf(acc1[mt][jt][0] + r0 - rmax[2 * mt]);
                float e1 = __expf(acc1[mt][jt][1] + r1 - rmax[2 * mt]);
                float e2 = __expf(acc1[mt][jt][2] + r0 - rmax[2 * mt + 1]);
                float e3 = __expf(acc1[mt][jt][3] + r1 - rmax[2 * mt + 1]);
                rsum[2 * mt] += e0 + e1; rsum[2 * mt + 1] += e2 + e3;
                int rowA = mw * 32 + mt * 16 + (lane >> 2);
                int rowB = rowA + 8;
                int unit = nw * 4 + jt;
                *(uint32_t*)(smem + AL_OFF + rowA * 256 + ((unit ^ (rowA & 7)) << 4) + (lane & 3) * 4)
                    = pack2(e0, e1);
                *(uint32_t*)(smem + AL_OFF + rowB * 256 + ((unit ^ (rowB & 7)) << 4) + (lane & 3) * 4)
                    = pack2(e2, e3);
            }
        #pragma unroll
        for (int r = 0; r < 4; r++) {
            rsum[r] += __shfl_xor_sync(~0u, rsum[r], 1);
            rsum[r] += __shfl_xor_sync(~0u, rsum[r], 2);
        }
        if ((lane & 3) == 0)
            #pragma unroll
            for (int r = 0; r < 4; r++) {
                int row = mw * 32 + (r >> 1) * 16 + (r & 1) * 8 + (lane >> 2);
                smf[SM_SSUM / 4 + row * 4 + nw] = rsum[r];
            }
        __syncthreads();
        if (nw == 0 && (lane & 3) == 0) {
            float bias = smf[SM_BIAS / 4];
            #pragma unroll
            for (int r = 0; r < 4; r++) {
                int row = mw * 32 + (r >> 1) * 16 + (r & 1) * 8 + (lane >> 2);
                float tot = smf[SM_SSUM / 4 + row * 4]     + smf[SM_SSUM / 4 + row * 4 + 1]
                          + smf[SM_SSUM / 4 + row * 4 + 2] + smf[SM_SSUM / 4 + row * 4 + 3];
                smf[SM_SINV / 4 + row] = 1.0f / tot;
                smf[SM_M / 4 + row] = rmax[r] + smf[SM_ROWC / 4 + row] + bias;
            }
        }
        __syncthreads();

        // ---- beta prep: Ml = max m, w = exp(m-Ml), zl = sum w ----
        if (tid < 64) {
            float vm = smf[SM_M / 4 + tid];
            for (int o = 16; o; o >>= 1) vm = fmaxf(vm, __shfl_xor_sync(~0u, vm, o));
            if ((tid & 31) == 0) smf[SM_ZML / 4 + (tid >> 5)] = vm;
        }
        __syncthreads();
        const float Ml = fmaxf(smf[SM_ZML / 4], smf[SM_ZML / 4 + 1]);
        if (tid < 64) {
            float wv = __expf(smf[SM_M / 4 + tid] - Ml);
            smf[SM_WB / 4 + tid] = wv;
            for (int o = 16; o; o >>= 1) wv += __shfl_xor_sync(~0u, wv, o);
            if ((tid & 31) == 0) smf[SM_ZML / 4 + 2 + (tid >> 5)] = wv;
        }
        __syncthreads();
        if (tid == 0) {
            g_Ml[chunk_idx] = Ml;
            g_zl[chunk_idx] = smf[SM_ZML / 4 + 2] + smf[SM_ZML / 4 + 3];
        }

        // ---- GEMM2: D = E @ qry ; M=64, warp n-tile 64 (slot nw), K=128 ----
        float iv[4];
        #pragma unroll
        for (int r = 0; r < 4; r++) {
            int row = mw * 32 + (r >> 1) * 16 + (r & 1) * 8 + (lane >> 2);
            iv[r] = smf[SM_SINV / 4 + row];
        }
        uint32_t rA2b[2], xA2[2];
        #pragma unroll
        for (int mt = 0; mt < 2; mt++) {
            int row = mw * 32 + mt * 16 + gb * 8 + l7;
            rA2b[mt] = row * 256; xA2[mt] = row & 7;
        }
        const uint32_t Bs = sb + B1_OFF + nw * 16384;
        const int qbase = gb * 8 + l7;

        float acc2[8][2][4];
        #pragma unroll
        for (int jj = 0; jj < 8; jj++)
            #pragma unroll
            for (int mt = 0; mt < 2; mt++)
                #pragma unroll
                for (int e = 0; e < 4; e++) acc2[jj][mt][e] = 0.f;

        #pragma unroll
        for (int s = 0; s < 8; s++) {
            uint32_t a[2][4];
            #pragma unroll
            for (int mt = 0; mt < 2; mt++) {
                uint32_t u = 2 * s + gh;
                LDSM4(a[mt][0], a[mt][1], a[mt][2], a[mt][3],
                      sb + AL_OFF + rA2b[mt] + ((u ^ xA2[mt]) << 4));
            }
            uint32_t bt[4][4];
            uint32_t qrow = (uint32_t)(s * 16 + qbase);
            #pragma unroll
            for (int t = 0; t < 4; t++) {
                uint32_t u = 2 * t + gh;
                LDSM4T(bt[t][0], bt[t][1], bt[t][2], bt[t][3],
                       Bs + qrow * 128 + ((u ^ (uint32_t)l7) << 4));
            }
            #pragma unroll
            for (int mt = 0; mt < 2; mt++)
                #pragma unroll
                for (int t = 0; t < 4; t++) {
                    mma16(acc2[2 * t][mt],     a[mt][0], a[mt][1], a[mt][2], a[mt][3], bt[t][0], bt[t][1]);
                    mma16(acc2[2 * t + 1][mt], a[mt][0], a[mt][1], a[mt][2], a[mt][3], bt[t][2], bt[t][3]);
                }
        }
        __syncthreads();   // all GEMM2 alpha reads done before EPI overwrite

        // ---- epilogue: stage a-tile per 32-row half, drain coalesced,
        //      accumulate beta-weighted ctx partials (s_l) on the fly ----
        float sacc[4] = { 0.f, 0.f, 0.f, 0.f };
        #pragma unroll
        for (int p = 0; p < 2; p++) {
            if (mw == p) {
                #pragma unroll
                for (int mt = 0; mt < 2; mt++)
                    #pragma unroll
                    for (int h = 0; h < 2; h++) {
                        int rl = mt * 16 + h * 8 + (lane >> 2);
                        float ivr = iv[mt * 2 + h];
                        #pragma unroll
                        for (int jj = 0; jj < 8; jj++) {
                            int col = nw * 64 + jj * 8 + 2 * (lane & 3);
                            *(float2*)(smem + EPI_OFF + rl * EPI_STR + col * 4) =
                                make_float2(acc2[jj][mt][2 * h] * ivr,
                                            acc2[jj][mt][2 * h + 1] * ivr);
                        }
                    }
            }
            __syncthreads();
            #pragma unroll
            for (int i = 0; i < 8; i++) {
                int idx = i * 256 + tid;
                int rl = idx >> 6, c4 = (idx & 63) * 4;
                float4 av = *(const float4*)(smem + EPI_OFF + rl * EPI_STR + c4 * 4);
                int row = p * 32 + rl;
                float4 cv = *(const float4*)(ctxb + row * 256 + c4);
                float wr = smf[SM_WB / 4 + row];
                sacc[0] += wr * cv.x; sacc[1] += wr * cv.y;
                sacc[2] += wr * cv.z; sacc[3] += wr * cv.w;
                float* o = out + obase + (size_t)row * 1024 + c4;
                __stcs((float4*)(o + 256), av);
                __stcs((float4*)(o + 512), make_float4(cv.x * av.x, cv.y * av.y,
                                                       cv.z * av.z, cv.w * av.w));
            }
            __syncthreads();
        }
        // reduce s partials: 4 row-groups x 256 cols
        *(float4*)(smem + SP_OFF + (tid >> 6) * 1024 + (tid & 63) * 16) =
            make_float4(sacc[0], sacc[1], sacc[2], sacc[3]);
        __syncthreads();
        {
            float s = *(const float*)(smem + SP_OFF + tid * 4)
                    + *(const float*)(smem + SP_OFF + 1024 + tid * 4)
                    + *(const float*)(smem + SP_OFF + 2048 + tid * 4)
                    + *(const float*)(smem + SP_OFF + 3072 + tid * 4);
            g_spart[(size_t)chunk_idx * 256 + tid] = s;
        }
        __syncthreads();
    }

    // ======== fused out3 tail: 8-way parallel per batch, batch-local spin ========
    __threadfence();                        // release g_spart/g_Ml/g_zl writes
    if (tid == 0) {
        atomicAdd(&g_cnt[b], 1);
        volatile int* vc = &g_cnt[b];
        while (*vc < 8) __nanosleep(128);
    }
    __syncthreads();
    __threadfence();                        // acquire siblings' writes

    if (tid < 32) {
        float ml = (tid < 16) ? g_Ml[b * 16 + tid] : -1e30f;
        float M = ml;
        for (int o = 8; o; o >>= 1) M = fmaxf(M, __shfl_xor_sync(~0u, M, o));
        M = __shfl_sync(~0u, M, 0);
        float cf = (tid < 16) ? __expf(ml - M) : 0.f;
        if (tid < 16) smf[SM_COEF / 4 + tid] = cf;
        float dz = (tid < 16) ? cf * g_zl[b * 16 + tid] : 0.f;
        for (int o = 8; o; o >>= 1) dz += __shfl_xor_sync(~0u, dz, o);
        if (tid == 0) smf[SM_DSH / 4] = dz;
    }
    __syncthreads();
    {
        float acc = 0.f;
        #pragma unroll
        for (int l = 0; l < 16; l++)
            acc += smf[SM_COEF / 4 + l] * g_spart[(size_t)(b * 16 + l) * 256 + tid];
        smf[SM_BV / 4 + tid] = acc / smf[SM_DSH / 4];
    }
    __syncthreads();
    {
        const float* cb = ctx + ((size_t)(b * C_) + chalf * 128) * H_;
        float* ob = out + ((size_t)(b * C_) + chalf * 128) * 1024 + 768;
        #pragma unroll 4
        for (int i = 0; i < 32; i++) {
            int f = i * 256 + tid;
            int row = f >> 6, c4 = (f & 63) * 4;
            float4 cv = *(const float4*)(cb + (size_t)row * 256 + c4);
            float4 bb = *(const float4*)(smf + SM_BV / 4 + c4);
            __stcs((float4*)(ob + (size_t)row * 1024 + c4),
                   make_float4(cv.x * bb.x, cv.y * bb.y, cv.z * bb.z, cv.w * bb.w));
        }
    }
    // phase-2 count: last of 16 arrivals resets counter for next graph replay
    if (tid == 0) {
        int r = atomicAdd(&g_cnt[b], 1);    // values 8..15
        if (r == 15) g_cnt[b] = 0;
    }
}

extern "C" void kernel_launch(void* const* d_in, const int* in_sizes, int n_in,
                              void* d_out, int out_size)
{
    const float* ctx  = (const float*)d_in[0];
    const float* qry  = (const float*)d_in[2];
    const float* attw = (const float*)d_in[4];
    const float* attb = (const float*)d_in[5];
    float* out = (float*)d_out;

    cudaFuncSetAttribute(k1_main, cudaFuncAttributeMaxDynamicSharedMemorySize, SMEM_TOTAL);
    k1_main<<<512, 256, SMEM_TOTAL>>>(ctx, qry, attw, attb, out);
}